// round 4
// baseline (speedup 1.0000x reference)
#include <cuda_runtime.h>
#include <math.h>

#define BB 32
#define TT 200
#define HH 2048
#define G4 8192   // 4*H
#define SS 256
#define TB 6400   // T*B
#define FF 20

// ---- scratch (device globals: allocation-free rule) ----
__device__ __align__(128) float g_fused[TB * FF];
__device__ __align__(128) float g_X[TB * HH];                 // [tb][h]
__device__ __align__(128) float g_preg[(size_t)TB * G4];      // [tb][j]
__device__ __align__(128) float g_h0T[HH * BB];               // [k][b] transposed h0
__device__ __align__(128) float g_cT[HH * BB];                // [u][b] transposed c
__device__ __align__(128) float g_hall[(size_t)TT * HH * BB]; // [t][u][b] h per step (transposed)

// ---------------- init h/c (transposed) ----------------
__global__ void k_init(const float* __restrict__ h0, const float* __restrict__ c0) {
    int i = blockIdx.x * blockDim.x + threadIdx.x;
    if (i < HH * BB) {
        int b = i / HH, k = i % HH;
        g_h0T[k * BB + b] = h0[i];
        g_cT[k * BB + b] = c0[i];
    }
}

// ---------------- fused = [x1@m1^T+b1 , x2@m2^T+b2] ----------------
__global__ void k_fused(const float* __restrict__ in1, const float* __restrict__ in2,
                        const float* __restrict__ m1W, const float* __restrict__ m1b,
                        const float* __restrict__ m2W, const float* __restrict__ m2b) {
    int idx = blockIdx.x * blockDim.x + threadIdx.x;  // idx = t*B + b
    if (idx >= TB) return;
    int t = idx / BB, b = idx % BB;
    float x0 = in1[(b * TT + t) * 2 + 0];
    float x1 = in1[(b * TT + t) * 2 + 1];
    float x2 = in2[b * TT + t];
#pragma unroll
    for (int j = 0; j < 10; j++)
        g_fused[idx * FF + j] = m1W[j * 2] * x0 + m1W[j * 2 + 1] * x1 + m1b[j];
#pragma unroll
    for (int j = 0; j < 10; j++)
        g_fused[idx * FF + 10 + j] = m2W[j] * x2 + m2b[j];
}

// ---------------- expert encode: X = fused @ enc_W[skill] + enc_b[skill] ----------------
__global__ __launch_bounds__(256) void k_encode(const float* __restrict__ encW,
                                                const float* __restrict__ encb,
                                                const int* __restrict__ routers) {
    int idx = blockIdx.x;  // tb
    int t = idx / BB, b = idx % BB;
    int skill = routers[b * TT + t];
    __shared__ float sf[FF];
    if (threadIdx.x < FF) sf[threadIdx.x] = g_fused[idx * FF + threadIdx.x];
    __syncthreads();
    const float* Wbase = encW + (size_t)skill * FF * HH;
    const float* bbase = encb + skill * HH;
    for (int h = threadIdx.x; h < HH; h += 256) {
        float acc = bbase[h];
#pragma unroll
        for (int f = 0; f < FF; f++) acc += sf[f] * Wbase[f * HH + h];
        g_X[idx * HH + h] = acc;
    }
}

// ---------------- pregates = X @ Wih^T + (bih+bhh)  [6400 x 8192] ----------------
__global__ __launch_bounds__(256) void k_pregemm(const float* __restrict__ Wih,
                                                 const float* __restrict__ bih,
                                                 const float* __restrict__ bhh) {
    __shared__ __align__(16) float As[16][68];
    __shared__ __align__(16) float Bs[16][68];
    int m0 = blockIdx.y * 64, n0 = blockIdx.x * 64;
    int tid = threadIdx.x;
    int tn = tid & 15, tm = tid >> 4;
    int lrow = tid >> 2;
    int lkq = (tid & 3) * 4;
    float acc[4][4] = {};

    for (int k0 = 0; k0 < HH; k0 += 16) {
        float4 av = *(const float4*)&g_X[(m0 + lrow) * HH + k0 + lkq];
        float4 bv = *(const float4*)&Wih[(size_t)(n0 + lrow) * HH + k0 + lkq];
        As[lkq + 0][lrow] = av.x; As[lkq + 1][lrow] = av.y;
        As[lkq + 2][lrow] = av.z; As[lkq + 3][lrow] = av.w;
        Bs[lkq + 0][lrow] = bv.x; Bs[lkq + 1][lrow] = bv.y;
        Bs[lkq + 2][lrow] = bv.z; Bs[lkq + 3][lrow] = bv.w;
        __syncthreads();
#pragma unroll
        for (int k = 0; k < 16; k++) {
            float4 a = *(const float4*)&As[k][tm * 4];
            float4 bq = *(const float4*)&Bs[k][tn * 4];
            acc[0][0] += a.x * bq.x; acc[0][1] += a.x * bq.y; acc[0][2] += a.x * bq.z; acc[0][3] += a.x * bq.w;
            acc[1][0] += a.y * bq.x; acc[1][1] += a.y * bq.y; acc[1][2] += a.y * bq.z; acc[1][3] += a.y * bq.w;
            acc[2][0] += a.z * bq.x; acc[2][1] += a.z * bq.y; acc[2][2] += a.z * bq.z; acc[2][3] += a.z * bq.w;
            acc[3][0] += a.w * bq.x; acc[3][1] += a.w * bq.y; acc[3][2] += a.w * bq.z; acc[3][3] += a.w * bq.w;
        }
        __syncthreads();
    }
    int n = n0 + tn * 4;
    float b0 = bih[n + 0] + bhh[n + 0];
    float b1 = bih[n + 1] + bhh[n + 1];
    float b2 = bih[n + 2] + bhh[n + 2];
    float b3 = bih[n + 3] + bhh[n + 3];
#pragma unroll
    for (int i = 0; i < 4; i++) {
        int m = m0 + tm * 4 + i;
        float4 o;
        o.x = acc[i][0] + b0; o.y = acc[i][1] + b1;
        o.z = acc[i][2] + b2; o.w = acc[i][3] + b3;
        *(float4*)&g_preg[(size_t)m * G4 + n] = o;
    }
}

// ---------------- per-step fused: gates = preg + h@Whh^T ; LSTM elementwise ----------------
// h is double-buffered through g_hall: read h_{t-1} (or g_h0T), write h_t.
// No block writes anything another block reads within the same launch.
__global__ __launch_bounds__(256) void k_step(const float* __restrict__ Whh, int t) {
    const float* __restrict__ hin =
        (t == 0) ? g_h0T : &g_hall[(size_t)(t - 1) * HH * BB];
    float* __restrict__ hout = &g_hall[(size_t)t * HH * BB];

    __shared__ __align__(16) float As[16][32];
    __shared__ __align__(16) float Bs[16][68];
    __shared__ __align__(16) float gs[32][65];
    int u0 = blockIdx.x * 16;
    int tid = threadIdx.x;
    int tn = tid & 31, tm = tid >> 5;
    int brow = tid >> 2;
    int bg = brow >> 4;
    int bu = brow & 15;
    int bj = bg * HH + u0 + bu;
    int bkq = (tid & 3) * 4;
    float acc[4][2] = {};

    for (int k0 = 0; k0 < HH; k0 += 16) {
#pragma unroll
        for (int l = 0; l < 2; l++) {
            int e = tid + l * 256;
            As[e >> 5][e & 31] = hin[(k0 + (e >> 5)) * BB + (e & 31)];
        }
        float4 bv = *(const float4*)&Whh[(size_t)bj * HH + k0 + bkq];
        Bs[bkq + 0][brow] = bv.x; Bs[bkq + 1][brow] = bv.y;
        Bs[bkq + 2][brow] = bv.z; Bs[bkq + 3][brow] = bv.w;
        __syncthreads();
#pragma unroll
        for (int k = 0; k < 16; k++) {
            float4 a = *(const float4*)&As[k][tm * 4];
            float2 bq = *(const float2*)&Bs[k][tn * 2];
            acc[0][0] += a.x * bq.x; acc[0][1] += a.x * bq.y;
            acc[1][0] += a.y * bq.x; acc[1][1] += a.y * bq.y;
            acc[2][0] += a.z * bq.x; acc[2][1] += a.z * bq.y;
            acc[3][0] += a.w * bq.x; acc[3][1] += a.w * bq.y;
        }
        __syncthreads();
    }

#pragma unroll
    for (int i = 0; i < 4; i++) {
        int b = tm * 4 + i;
        const float* pr = &g_preg[(size_t)(t * BB + b) * G4];
#pragma unroll
        for (int j = 0; j < 2; j++) {
            int n = tn * 2 + j;
            int gate = n >> 4, uu = n & 15;
            gs[b][n] = acc[i][j] + pr[gate * HH + u0 + uu];
        }
    }
    __syncthreads();

#pragma unroll
    for (int l = 0; l < 2; l++) {
        int p = tid + l * 256;
        int b = p & 31, uu = p >> 5;
        float gi = gs[b][uu];
        float gf = gs[b][16 + uu];
        float gg = gs[b][32 + uu];
        float go = gs[b][48 + uu];
        float si = 1.0f / (1.0f + expf(-gi));
        float sf_ = 1.0f / (1.0f + expf(-gf));
        float so = 1.0f / (1.0f + expf(-go));
        float tg = tanhf(gg);
        int u = u0 + uu;
        float c = sf_ * g_cT[u * BB + b] + si * tg;
        float hnew = so * tanhf(c);
        g_cT[u * BB + b] = c;
        hout[u * BB + b] = hnew;
    }
}

// ---------------- decoder: out[b*T+t][s] = h_t[b] . dec_W[s] + dec_b[s] ----------------
__global__ __launch_bounds__(256) void k_dec(const float* __restrict__ decW,
                                             const float* __restrict__ decb,
                                             float* __restrict__ out) {
    __shared__ __align__(16) float As[16][32];
    __shared__ __align__(16) float Bs[16][68];
    int t = blockIdx.y, s0 = blockIdx.x * 64;
    int tid = threadIdx.x;
    int tn = tid & 31, tm = tid >> 5;
    int brow = tid >> 2;
    int bkq = (tid & 3) * 4;
    float acc[4][2] = {};

    for (int k0 = 0; k0 < HH; k0 += 16) {
#pragma unroll
        for (int l = 0; l < 2; l++) {
            int e = tid + l * 256;
            As[e >> 5][e & 31] = g_hall[((size_t)t * HH + k0 + (e >> 5)) * BB + (e & 31)];
        }
        float4 bv = *(const float4*)&decW[(size_t)(s0 + brow) * HH + k0 + bkq];
        Bs[bkq + 0][brow] = bv.x; Bs[bkq + 1][brow] = bv.y;
        Bs[bkq + 2][brow] = bv.z; Bs[bkq + 3][brow] = bv.w;
        __syncthreads();
#pragma unroll
        for (int k = 0; k < 16; k++) {
            float4 a = *(const float4*)&As[k][tm * 4];
            float2 bq = *(const float2*)&Bs[k][tn * 2];
            acc[0][0] += a.x * bq.x; acc[0][1] += a.x * bq.y;
            acc[1][0] += a.y * bq.x; acc[1][1] += a.y * bq.y;
            acc[2][0] += a.z * bq.x; acc[2][1] += a.z * bq.y;
            acc[3][0] += a.w * bq.x; acc[3][1] += a.w * bq.y;
        }
        __syncthreads();
    }
#pragma unroll
    for (int i = 0; i < 4; i++) {
        int b = tm * 4 + i;
#pragma unroll
        for (int j = 0; j < 2; j++) {
            int s = s0 + tn * 2 + j;
            out[(b * TT + t) * SS + s] = acc[i][j] + decb[s];
        }
    }
}

// ---------------- final state write-out ----------------
__global__ void k_finish(float* __restrict__ out, int out_size) {
    int i = blockIdx.x * blockDim.x + threadIdx.x;
    if (i < HH * BB) {
        int b = i / HH, k = i % HH;
        int base = TB * SS;
        const float* hlast = &g_hall[(size_t)(TT - 1) * HH * BB];
        if (base + i < out_size) out[base + i] = hlast[k * BB + b];
        if (base + HH * BB + i < out_size) out[base + HH * BB + i] = g_cT[k * BB + b];
    }
}

extern "C" void kernel_launch(void* const* d_in, const int* in_sizes, int n_in,
                              void* d_out, int out_size) {
    const float* in1  = (const float*)d_in[0];
    const float* in2  = (const float*)d_in[1];
    const float* h0   = (const float*)d_in[2];
    const float* c0   = (const float*)d_in[3];
    const int*   rt   = (const int*)  d_in[4];
    const float* m1W  = (const float*)d_in[5];
    const float* m1b  = (const float*)d_in[6];
    const float* m2W  = (const float*)d_in[7];
    const float* m2b  = (const float*)d_in[8];
    const float* encW = (const float*)d_in[9];
    const float* encb = (const float*)d_in[10];
    const float* Wih  = (const float*)d_in[11];
    const float* Whh  = (const float*)d_in[12];
    const float* bih  = (const float*)d_in[13];
    const float* bhh  = (const float*)d_in[14];
    const float* decW = (const float*)d_in[15];
    const float* decb = (const float*)d_in[16];
    float* out = (float*)d_out;

    k_init<<<(HH * BB + 255) / 256, 256>>>(h0, c0);
    k_fused<<<(TB + 127) / 128, 128>>>(in1, in2, m1W, m1b, m2W, m2b);
    k_encode<<<TB, 256>>>(encW, encb, rt);
    k_pregemm<<<dim3(G4 / 64, TB / 64), 256>>>(Wih, bih, bhh);
    for (int t = 0; t < TT; t++)
        k_step<<<HH / 16, 256>>>(Whh, t);
    k_dec<<<dim3(SS / 64, TT), 256>>>(decW, decb, out);
    k_finish<<<(HH * BB + 255) / 256, 256>>>(out, out_size);
}

// round 5
// speedup vs baseline: 1.2600x; 1.2600x over previous
#include <cuda_runtime.h>
#include <math.h>

#define BB 32
#define TT 200
#define HH 2048
#define G4 8192   // 4*H
#define SS 256
#define TB 6400   // T*B
#define FF 20

typedef unsigned long long ull;

// ---- f32x2 packed-FMA helpers (sm_103a FFMA2, PTX-only) ----
__device__ __forceinline__ ull pk2(float lo, float hi) {
    ull r; asm("mov.b64 %0, {%1, %2};" : "=l"(r) : "f"(lo), "f"(hi)); return r;
}
__device__ __forceinline__ void fma2(ull& d, ull a, ull b) {
    asm("fma.rn.f32x2 %0, %1, %2, %0;" : "+l"(d) : "l"(a), "l"(b));
}
__device__ __forceinline__ float2 up2(ull v) {
    float2 r; asm("mov.b64 {%0, %1}, %2;" : "=f"(r.x), "=f"(r.y) : "l"(v)); return r;
}

// ---- scratch (device globals: allocation-free rule) ----
__device__ __align__(128) float g_fused[TB * FF];
__device__ __align__(128) float g_X[TB * HH];                 // [tb][h]
__device__ __align__(128) float g_preg[(size_t)TB * G4];      // [tb][j]
__device__ __align__(128) float g_h0T[HH * BB];               // [k][b] transposed h0
__device__ __align__(128) float g_cT[HH * BB];                // [u][b] transposed c
__device__ __align__(128) float g_hall[(size_t)TT * HH * BB]; // [t][u][b]

// ---------------- init h/c (transposed) ----------------
__global__ void k_init(const float* __restrict__ h0, const float* __restrict__ c0) {
    int i = blockIdx.x * blockDim.x + threadIdx.x;
    if (i < HH * BB) {
        int b = i / HH, k = i % HH;
        g_h0T[k * BB + b] = h0[i];
        g_cT[k * BB + b] = c0[i];
    }
}

// ---------------- fused = [x1@m1^T+b1 , x2@m2^T+b2] ----------------
__global__ void k_fused(const float* __restrict__ in1, const float* __restrict__ in2,
                        const float* __restrict__ m1W, const float* __restrict__ m1b,
                        const float* __restrict__ m2W, const float* __restrict__ m2b) {
    int idx = blockIdx.x * blockDim.x + threadIdx.x;  // idx = t*B + b
    if (idx >= TB) return;
    int t = idx / BB, b = idx % BB;
    float x0 = in1[(b * TT + t) * 2 + 0];
    float x1 = in1[(b * TT + t) * 2 + 1];
    float x2 = in2[b * TT + t];
#pragma unroll
    for (int j = 0; j < 10; j++)
        g_fused[idx * FF + j] = m1W[j * 2] * x0 + m1W[j * 2 + 1] * x1 + m1b[j];
#pragma unroll
    for (int j = 0; j < 10; j++)
        g_fused[idx * FF + 10 + j] = m2W[j] * x2 + m2b[j];
}

// ---------------- expert encode: X = fused @ enc_W[skill] + enc_b[skill] ----------------
__global__ __launch_bounds__(256) void k_encode(const float* __restrict__ encW,
                                                const float* __restrict__ encb,
                                                const int* __restrict__ routers) {
    int idx = blockIdx.x;  // tb
    int t = idx / BB, b = idx % BB;
    int skill = routers[b * TT + t];
    __shared__ float sf[FF];
    if (threadIdx.x < FF) sf[threadIdx.x] = g_fused[idx * FF + threadIdx.x];
    __syncthreads();
    const float* Wbase = encW + (size_t)skill * FF * HH;
    const float* bbase = encb + skill * HH;
    for (int h = threadIdx.x; h < HH; h += 256) {
        float acc = bbase[h];
#pragma unroll
        for (int f = 0; f < FF; f++) acc += sf[f] * Wbase[f * HH + h];
        g_X[idx * HH + h] = acc;
    }
}

// ---------------- pregates = X @ Wih^T + (bih+bhh)  [6400 x 8192] ----------------
// 128x128 block tile, K-chunk 16, 8x8 thread tile, FFMA2 packed over row pairs.
__global__ __launch_bounds__(256, 2) void k_pregemm(const float* __restrict__ Wih,
                                                    const float* __restrict__ bih,
                                                    const float* __restrict__ bhh) {
    __shared__ __align__(16) float As[16][132];
    __shared__ __align__(16) float Bs[16][132];
    int m0 = blockIdx.y * 128, n0 = blockIdx.x * 128;
    int tid = threadIdx.x;
    int tm = tid >> 4, tn = tid & 15;   // 16x16 thread grid, each 8x8
    int lr = tid >> 2;                   // 0..63 (+64 on second load)
    int lkq = (tid & 3) * 4;             // 0,4,8,12

    // bias (per-column, 8 cols)
    float bsum[8];
#pragma unroll
    for (int j = 0; j < 8; j++) {
        int n = n0 + tn * 8 + j;
        bsum[j] = bih[n] + bhh[n];
    }

    ull acc[4][8] = {};   // [row-pair][col], packed f32x2 over rows

    for (int k0 = 0; k0 < HH; k0 += 16) {
#pragma unroll
        for (int l = 0; l < 2; l++) {
            int row = lr + l * 64;
            float4 av = *(const float4*)&g_X[(size_t)(m0 + row) * HH + k0 + lkq];
            float4 bv = *(const float4*)&Wih[(size_t)(n0 + row) * HH + k0 + lkq];
            As[lkq + 0][row] = av.x; As[lkq + 1][row] = av.y;
            As[lkq + 2][row] = av.z; As[lkq + 3][row] = av.w;
            Bs[lkq + 0][row] = bv.x; Bs[lkq + 1][row] = bv.y;
            Bs[lkq + 2][row] = bv.z; Bs[lkq + 3][row] = bv.w;
        }
        __syncthreads();
#pragma unroll
        for (int k = 0; k < 16; k++) {
            float4 a0 = *(const float4*)&As[k][tm * 8];
            float4 a1 = *(const float4*)&As[k][tm * 8 + 4];
            float4 b0 = *(const float4*)&Bs[k][tn * 8];
            float4 b1 = *(const float4*)&Bs[k][tn * 8 + 4];
            ull ap[4];
            ap[0] = pk2(a0.x, a0.y); ap[1] = pk2(a0.z, a0.w);
            ap[2] = pk2(a1.x, a1.y); ap[3] = pk2(a1.z, a1.w);
            float bb[8] = {b0.x, b0.y, b0.z, b0.w, b1.x, b1.y, b1.z, b1.w};
#pragma unroll
            for (int j = 0; j < 8; j++) {
                ull bd = pk2(bb[j], bb[j]);
#pragma unroll
                for (int p = 0; p < 4; p++) fma2(acc[p][j], ap[p], bd);
            }
        }
        __syncthreads();
    }

    // epilogue: unpack row pairs, add bias, store 2 float4 per row
#pragma unroll
    for (int p = 0; p < 4; p++) {
        float2 c[8];
#pragma unroll
        for (int j = 0; j < 8; j++) c[j] = up2(acc[p][j]);
#pragma unroll
        for (int rr = 0; rr < 2; rr++) {
            int m = m0 + tm * 8 + p * 2 + rr;
            float v[8];
#pragma unroll
            for (int j = 0; j < 8; j++) v[j] = (rr ? c[j].y : c[j].x) + bsum[j];
            float4 o0 = make_float4(v[0], v[1], v[2], v[3]);
            float4 o1 = make_float4(v[4], v[5], v[6], v[7]);
            *(float4*)&g_preg[(size_t)m * G4 + n0 + tn * 8]     = o0;
            *(float4*)&g_preg[(size_t)m * G4 + n0 + tn * 8 + 4] = o1;
        }
    }
}

// ---------------- per-step fused: gates = preg + h@Whh^T ; LSTM elementwise ----------------
// 512 threads: 2 warp-groups split K (each 1024), FFMA2 over batch pairs.
// h double-buffered through g_hall (read h_{t-1}, write h_t) -> no cross-block race.
__global__ __launch_bounds__(512) void k_step(const float* __restrict__ Whh, int t) {
    const float* __restrict__ hin =
        (t == 0) ? g_h0T : &g_hall[(size_t)(t - 1) * HH * BB];
    float* __restrict__ hout = &g_hall[(size_t)t * HH * BB];

    __shared__ __align__(16) float As[2][16][32];
    __shared__ __align__(16) float Bs[2][16][68];
    __shared__ float gs[32][65];

    int u0 = blockIdx.x * 16;
    int tid = threadIdx.x;
    int kw = tid >> 8;        // K-half: 0 or 1
    int lt = tid & 255;
    int tn = lt & 31, tm = lt >> 5;   // 2 cols, 4 batches (2 pairs)
    int brow = lt >> 2;               // 0..63 (column being loaded)
    int bj = (brow >> 4) * HH + u0 + (brow & 15);  // Whh row for this column
    int bkq = (lt & 3) * 4;

    ull acc[2][2] = {};   // [batch-pair][col]

    int kbase = kw * 1024;
    for (int kc = 0; kc < 1024; kc += 16) {
        int k0 = kbase + kc;
#pragma unroll
        for (int l = 0; l < 2; l++) {
            int e = lt + l * 256;
            As[kw][e >> 5][e & 31] = hin[(k0 + (e >> 5)) * BB + (e & 31)];
        }
        float4 bv = *(const float4*)&Whh[(size_t)bj * HH + k0 + bkq];
        Bs[kw][bkq + 0][brow] = bv.x; Bs[kw][bkq + 1][brow] = bv.y;
        Bs[kw][bkq + 2][brow] = bv.z; Bs[kw][bkq + 3][brow] = bv.w;
        __syncthreads();
#pragma unroll
        for (int k = 0; k < 16; k++) {
            float4 a = *(const float4*)&As[kw][k][tm * 4];
            float2 b = *(const float2*)&Bs[kw][k][tn * 2];
            ull ap0 = pk2(a.x, a.y), ap1 = pk2(a.z, a.w);
            ull bd0 = pk2(b.x, b.x), bd1 = pk2(b.y, b.y);
            fma2(acc[0][0], ap0, bd0); fma2(acc[0][1], ap0, bd1);
            fma2(acc[1][0], ap1, bd0); fma2(acc[1][1], ap1, bd1);
        }
        __syncthreads();
    }

    // combine halves: kw=1 writes partials, kw=0 adds + pregates
    if (kw == 1) {
#pragma unroll
        for (int p = 0; p < 2; p++) {
#pragma unroll
            for (int j = 0; j < 2; j++) {
                float2 v = up2(acc[p][j]);
                int n = tn * 2 + j;
                gs[tm * 4 + p * 2 + 0][n] = v.x;
                gs[tm * 4 + p * 2 + 1][n] = v.y;
            }
        }
    }
    __syncthreads();
    if (kw == 0) {
#pragma unroll
        for (int p = 0; p < 2; p++) {
#pragma unroll
            for (int j = 0; j < 2; j++) {
                float2 v = up2(acc[p][j]);
                int n = tn * 2 + j;
                int gate = n >> 4, uu = n & 15;
                int b0i = tm * 4 + p * 2;
                const float* pr0 = &g_preg[(size_t)(t * BB + b0i) * G4 + gate * HH + u0 + uu];
                const float* pr1 = &g_preg[(size_t)(t * BB + b0i + 1) * G4 + gate * HH + u0 + uu];
                gs[b0i + 0][n] += v.x + pr0[0];
                gs[b0i + 1][n] += v.y + pr1[0];
            }
        }
    }
    __syncthreads();

    // LSTM elementwise: 512 (b,u) pairs, 1 per thread
    {
        int b = tid & 31, uu = tid >> 5;  // uu 0..15
        float gi = gs[b][uu];
        float gf = gs[b][16 + uu];
        float gg = gs[b][32 + uu];
        float go = gs[b][48 + uu];
        float si = 1.0f / (1.0f + expf(-gi));
        float sf_ = 1.0f / (1.0f + expf(-gf));
        float so = 1.0f / (1.0f + expf(-go));
        float tg = tanhf(gg);
        int u = u0 + uu;
        float c = sf_ * g_cT[u * BB + b] + si * tg;
        float hnew = so * tanhf(c);
        g_cT[u * BB + b] = c;
        hout[u * BB + b] = hnew;
    }
}

// ---------------- decoder: out[b*T+t][s] = h_t[b] . dec_W[s] + dec_b[s] ----------------
__global__ __launch_bounds__(256) void k_dec(const float* __restrict__ decW,
                                             const float* __restrict__ decb,
                                             float* __restrict__ out) {
    __shared__ __align__(16) float As[16][32];
    __shared__ __align__(16) float Bs[16][68];
    int t = blockIdx.y, s0 = blockIdx.x * 64;
    int tid = threadIdx.x;
    int tn = tid & 31, tm = tid >> 5;
    int brow = tid >> 2;
    int bkq = (tid & 3) * 4;
    ull acc[2][2] = {};

    for (int k0 = 0; k0 < HH; k0 += 16) {
#pragma unroll
        for (int l = 0; l < 2; l++) {
            int e = tid + l * 256;
            As[e >> 5][e & 31] = g_hall[((size_t)t * HH + k0 + (e >> 5)) * BB + (e & 31)];
        }
        float4 bv = *(const float4*)&decW[(size_t)(s0 + brow) * HH + k0 + bkq];
        Bs[bkq + 0][brow] = bv.x; Bs[bkq + 1][brow] = bv.y;
        Bs[bkq + 2][brow] = bv.z; Bs[bkq + 3][brow] = bv.w;
        __syncthreads();
#pragma unroll
        for (int k = 0; k < 16; k++) {
            float4 a = *(const float4*)&As[k][tm * 4];
            float2 b = *(const float2*)&Bs[k][tn * 2];
            ull ap0 = pk2(a.x, a.y), ap1 = pk2(a.z, a.w);
            ull bd0 = pk2(b.x, b.x), bd1 = pk2(b.y, b.y);
            fma2(acc[0][0], ap0, bd0); fma2(acc[0][1], ap0, bd1);
            fma2(acc[1][0], ap1, bd0); fma2(acc[1][1], ap1, bd1);
        }
        __syncthreads();
    }
#pragma unroll
    for (int p = 0; p < 2; p++) {
#pragma unroll
        for (int j = 0; j < 2; j++) {
            float2 v = up2(acc[p][j]);
            int s = s0 + tn * 2 + j;
            int b0i = tm * 4 + p * 2;
            out[(b0i * TT + t) * SS + s]       = v.x + decb[s];
            out[((b0i + 1) * TT + t) * SS + s] = v.y + decb[s];
        }
    }
}

// ---------------- final state write-out ----------------
__global__ void k_finish(float* __restrict__ out, int out_size) {
    int i = blockIdx.x * blockDim.x + threadIdx.x;
    if (i < HH * BB) {
        int b = i / HH, k = i % HH;
        int base = TB * SS;
        const float* hlast = &g_hall[(size_t)(TT - 1) * HH * BB];
        if (base + i < out_size) out[base + i] = hlast[k * BB + b];
        if (base + HH * BB + i < out_size) out[base + HH * BB + i] = g_cT[k * BB + b];
    }
}

extern "C" void kernel_launch(void* const* d_in, const int* in_sizes, int n_in,
                              void* d_out, int out_size) {
    const float* in1  = (const float*)d_in[0];
    const float* in2  = (const float*)d_in[1];
    const float* h0   = (const float*)d_in[2];
    const float* c0   = (const float*)d_in[3];
    const int*   rt   = (const int*)  d_in[4];
    const float* m1W  = (const float*)d_in[5];
    const float* m1b  = (const float*)d_in[6];
    const float* m2W  = (const float*)d_in[7];
    const float* m2b  = (const float*)d_in[8];
    const float* encW = (const float*)d_in[9];
    const float* encb = (const float*)d_in[10];
    const float* Wih  = (const float*)d_in[11];
    const float* Whh  = (const float*)d_in[12];
    const float* bih  = (const float*)d_in[13];
    const float* bhh  = (const float*)d_in[14];
    const float* decW = (const float*)d_in[15];
    const float* decb = (const float*)d_in[16];
    float* out = (float*)d_out;

    k_init<<<(HH * BB + 255) / 256, 256>>>(h0, c0);
    k_fused<<<(TB + 127) / 128, 128>>>(in1, in2, m1W, m1b, m2W, m2b);
    k_encode<<<TB, 256>>>(encW, encb, rt);
    k_pregemm<<<dim3(G4 / 128, TB / 128), 256>>>(Wih, bih, bhh);
    for (int t = 0; t < TT; t++)
        k_step<<<HH / 16, 512>>>(Whh, t);
    k_dec<<<dim3(SS / 64, TT), 256>>>(decW, decb, out);
    k_finish<<<(HH * BB + 255) / 256, 256>>>(out, out_size);
}

// round 6
// speedup vs baseline: 1.5576x; 1.2362x over previous
#include <cuda_runtime.h>
#include <math.h>
#include <stdint.h>

#define BB 32
#define TT 200
#define HH 2048
#define G4 8192   // 4*H
#define SS 256
#define TB 6400   // T*B
#define FF 20

typedef unsigned long long ull;

// ---- f32x2 packed-FMA helpers (sm_103a FFMA2, PTX-only) ----
__device__ __forceinline__ ull pk2(float lo, float hi) {
    ull r; asm("mov.b64 %0, {%1, %2};" : "=l"(r) : "f"(lo), "f"(hi)); return r;
}
__device__ __forceinline__ void fma2(ull& d, ull a, ull b) {
    asm("fma.rn.f32x2 %0, %1, %2, %0;" : "+l"(d) : "l"(a), "l"(b));
}
__device__ __forceinline__ float2 up2(ull v) {
    float2 r; asm("mov.b64 {%0, %1}, %2;" : "=f"(r.x), "=f"(r.y) : "l"(v)); return r;
}

// ---- cp.async helpers ----
__device__ __forceinline__ void cpa16(void* dst_smem, const void* src) {
    uint32_t d = (uint32_t)__cvta_generic_to_shared(dst_smem);
    asm volatile("cp.async.cg.shared.global [%0], [%1], 16;" :: "r"(d), "l"(src));
}
__device__ __forceinline__ void cp_commit() { asm volatile("cp.async.commit_group;"); }
__device__ __forceinline__ void cp_wait0()  { asm volatile("cp.async.wait_group 0;" ::: "memory"); }

// ---- scratch (device globals: allocation-free rule) ----
__device__ __align__(128) float g_fused[TB * FF];
__device__ __align__(128) float g_X[TB * HH];                 // [tb][h]
__device__ __align__(128) float g_XT[HH * TB];                // [k][m]
__device__ __align__(128) float g_WihT[HH * G4];              // [k][c], c = u*4+g
__device__ __align__(128) float g_WhhT[HH * G4];              // [k][c]
__device__ __align__(128) float g_preg[(size_t)TB * G4];      // [tb][c], c interleaved
__device__ __align__(128) float g_h0T[HH * BB];               // [k][b]
__device__ __align__(128) float g_cT[HH * BB];                // [u][b]
__device__ __align__(128) float g_hall[(size_t)TT * HH * BB]; // [t][u][b]

// ---------------- init h/c (transposed) ----------------
__global__ void k_init(const float* __restrict__ h0, const float* __restrict__ c0) {
    int i = blockIdx.x * blockDim.x + threadIdx.x;
    if (i < HH * BB) {
        int b = i / HH, k = i % HH;
        g_h0T[k * BB + b] = h0[i];
        g_cT[k * BB + b] = c0[i];
    }
}

// ---------------- fused = [x1@m1^T+b1 , x2@m2^T+b2] ----------------
__global__ void k_fused(const float* __restrict__ in1, const float* __restrict__ in2,
                        const float* __restrict__ m1W, const float* __restrict__ m1b,
                        const float* __restrict__ m2W, const float* __restrict__ m2b) {
    int idx = blockIdx.x * blockDim.x + threadIdx.x;  // idx = t*B + b
    if (idx >= TB) return;
    int t = idx / BB, b = idx % BB;
    float x0 = in1[(b * TT + t) * 2 + 0];
    float x1 = in1[(b * TT + t) * 2 + 1];
    float x2 = in2[b * TT + t];
#pragma unroll
    for (int j = 0; j < 10; j++)
        g_fused[idx * FF + j] = m1W[j * 2] * x0 + m1W[j * 2 + 1] * x1 + m1b[j];
#pragma unroll
    for (int j = 0; j < 10; j++)
        g_fused[idx * FF + 10 + j] = m2W[j] * x2 + m2b[j];
}

// ---------------- expert encode: X = fused @ enc_W[skill] + enc_b[skill] ----------------
__global__ __launch_bounds__(256) void k_encode(const float* __restrict__ encW,
                                                const float* __restrict__ encb,
                                                const int* __restrict__ routers) {
    int idx = blockIdx.x;  // tb
    int t = idx / BB, b = idx % BB;
    int skill = routers[b * TT + t];
    __shared__ float sf[FF];
    if (threadIdx.x < FF) sf[threadIdx.x] = g_fused[idx * FF + threadIdx.x];
    __syncthreads();
    const float* Wbase = encW + (size_t)skill * FF * HH;
    const float* bbase = encb + skill * HH;
    for (int h = threadIdx.x; h < HH; h += 256) {
        float acc = bbase[h];
#pragma unroll
        for (int f = 0; f < FF; f++) acc += sf[f] * Wbase[f * HH + h];
        g_X[idx * HH + h] = acc;
    }
}

// ---------------- weight transpose with gate interleave: out[k][c], c=u*4+g ----------------
__global__ void k_wt(const float* __restrict__ W, float* __restrict__ out) {
    __shared__ float s[32][33];
    int c0 = blockIdx.x * 32, k0 = blockIdx.y * 32;
    int tx = threadIdx.x, ty = threadIdx.y;
#pragma unroll
    for (int i = ty; i < 32; i += 8) {
        int c = c0 + i;
        int j = (c & 3) * HH + (c >> 2);
        s[i][tx] = W[(size_t)j * HH + k0 + tx];
    }
    __syncthreads();
#pragma unroll
    for (int i = ty; i < 32; i += 8)
        out[(size_t)(k0 + i) * G4 + c0 + tx] = s[tx][i];
}

// ---------------- X transpose: g_XT[k][m] ----------------
__global__ void k_xt() {
    __shared__ float s[32][33];
    int m0 = blockIdx.x * 32, k0 = blockIdx.y * 32;
    int tx = threadIdx.x, ty = threadIdx.y;
#pragma unroll
    for (int i = ty; i < 32; i += 8)
        s[i][tx] = g_X[(size_t)(m0 + i) * HH + k0 + tx];
    __syncthreads();
#pragma unroll
    for (int i = ty; i < 32; i += 8)
        g_XT[(size_t)(k0 + i) * TB + m0 + tx] = s[tx][i];
}

// ---------------- pregates = X @ Wih^T + (bih+bhh)  [6400 x 8192 interleaved] ----------------
// 128x128 tile, cp.async double-buffered, FFMA2 packed over row pairs.
__global__ __launch_bounds__(256, 2) void k_pregemm(const float* __restrict__ bih,
                                                    const float* __restrict__ bhh) {
    extern __shared__ float sm[];
    float* As = sm;            // [2][16][128]
    float* Bs = sm + 2 * 2048; // [2][16][128]
    int m0 = blockIdx.y * 128, n0 = blockIdx.x * 128;
    int tid = threadIdx.x;
    int tm = tid >> 4, tn = tid & 15;

    float bsum[8];
#pragma unroll
    for (int j = 0; j < 8; j++) {
        int c = n0 + tn * 8 + j;
        int jj = (c & 3) * HH + (c >> 2);
        bsum[j] = bih[jj] + bhh[jj];
    }

    ull acc[4][8] = {};  // [rowpair][col]

    // chunk mapping: q in [0,512): r=q>>5, c4=(q&31)*4 ; 2 chunks per thread per tile
    int r0 = (tid * 2) >> 5,       c40 = ((tid * 2) & 31) * 4;
    int r1 = (tid * 2 + 1) >> 5,   c41 = ((tid * 2 + 1) & 31) * 4;

    // prologue: chunk 0 -> buf 0
    cpa16(&As[0 * 2048 + r0 * 128 + c40], &g_XT[(size_t)(0 + r0) * TB + m0 + c40]);
    cpa16(&As[0 * 2048 + r1 * 128 + c41], &g_XT[(size_t)(0 + r1) * TB + m0 + c41]);
    cpa16(&Bs[0 * 2048 + r0 * 128 + c40], &g_WihT[(size_t)(0 + r0) * G4 + n0 + c40]);
    cpa16(&Bs[0 * 2048 + r1 * 128 + c41], &g_WihT[(size_t)(0 + r1) * G4 + n0 + c41]);
    cp_commit();

    const int NIT = HH / 16;  // 128
    for (int it = 0; it < NIT; it++) {
        int buf = it & 1;
        cp_wait0();
        __syncthreads();
        if (it + 1 < NIT) {
            int kn = (it + 1) * 16;
            int nb = buf ^ 1;
            cpa16(&As[nb * 2048 + r0 * 128 + c40], &g_XT[(size_t)(kn + r0) * TB + m0 + c40]);
            cpa16(&As[nb * 2048 + r1 * 128 + c41], &g_XT[(size_t)(kn + r1) * TB + m0 + c41]);
            cpa16(&Bs[nb * 2048 + r0 * 128 + c40], &g_WihT[(size_t)(kn + r0) * G4 + n0 + c40]);
            cpa16(&Bs[nb * 2048 + r1 * 128 + c41], &g_WihT[(size_t)(kn + r1) * G4 + n0 + c41]);
            cp_commit();
        }
        const float* A = &As[buf * 2048];
        const float* B = &Bs[buf * 2048];
#pragma unroll
        for (int k = 0; k < 16; k++) {
            float4 a0 = *(const float4*)&A[k * 128 + tm * 8];
            float4 a1 = *(const float4*)&A[k * 128 + tm * 8 + 4];
            float4 b0 = *(const float4*)&B[k * 128 + tn * 8];
            float4 b1 = *(const float4*)&B[k * 128 + tn * 8 + 4];
            ull ap[4];
            ap[0] = pk2(a0.x, a0.y); ap[1] = pk2(a0.z, a0.w);
            ap[2] = pk2(a1.x, a1.y); ap[3] = pk2(a1.z, a1.w);
            float bb[8] = {b0.x, b0.y, b0.z, b0.w, b1.x, b1.y, b1.z, b1.w};
#pragma unroll
            for (int j = 0; j < 8; j++) {
                ull bd = pk2(bb[j], bb[j]);
#pragma unroll
                for (int p = 0; p < 4; p++) fma2(acc[p][j], ap[p], bd);
            }
        }
        __syncthreads();
    }

#pragma unroll
    for (int p = 0; p < 4; p++) {
        float2 c[8];
#pragma unroll
        for (int j = 0; j < 8; j++) c[j] = up2(acc[p][j]);
#pragma unroll
        for (int rr = 0; rr < 2; rr++) {
            int m = m0 + tm * 8 + p * 2 + rr;
            float v[8];
#pragma unroll
            for (int j = 0; j < 8; j++) v[j] = (rr ? c[j].y : c[j].x) + bsum[j];
            *(float4*)&g_preg[(size_t)m * G4 + n0 + tn * 8]     = make_float4(v[0], v[1], v[2], v[3]);
            *(float4*)&g_preg[(size_t)m * G4 + n0 + tn * 8 + 4] = make_float4(v[4], v[5], v[6], v[7]);
        }
    }
}

// ---------------- per-step fused: gates = preg + h@Whh^T ; LSTM elementwise ----------------
// 512 threads = 4 K-slices x 128. Per-thread 4b x 4c, FFMA2 over col pairs.
// A tile stored duplicated in smem -> zero packing MOVs in inner loop.
__global__ __launch_bounds__(512) void k_step(int t) {
    extern __shared__ float sm[];
    // As2: 4 slices x 2 bufs x 16 x 64 (dup'd)   = 8192 floats
    // Bs : 4 slices x 2 bufs x 16 x 64           = 8192 floats
    // gsp: 4 x 32 x 65                            = 8320 floats
    const float* __restrict__ hin =
        (t == 0) ? g_h0T : &g_hall[(size_t)(t - 1) * HH * BB];
    float* __restrict__ hout = &g_hall[(size_t)t * HH * BB];

    int tid = threadIdx.x;
    int kw = tid >> 7;        // 0..3
    int lt = tid & 127;
    int tb = lt >> 4;         // 0..7 (4 batches each)
    int tc = lt & 15;         // 0..15 (4 cols each)
    int u0 = blockIdx.x * 16;
    int cbase = u0 * 4;

    float* As2 = sm + kw * 2048;          // [2][16][64]
    float* Bs  = sm + 8192 + kw * 2048;   // [2][16][64]
    float* gsp = sm + 16384;              // [4][32][65]

    int kbase = kw * 512;
    // A chunk: q=lt: r=lt>>3, ac=(lt&7)*4
    int ar = lt >> 3, ac = (lt & 7) * 4;
    // B chunks: q=lt*2+s: r=q>>4, c4=(q&15)*4
    int br0 = (lt * 2) >> 4,     bc0 = ((lt * 2) & 15) * 4;
    int br1 = (lt * 2 + 1) >> 4, bc1 = ((lt * 2 + 1) & 15) * 4;

    ull acc[4][2] = {};

    // prologue
    float4 av = *(const float4*)&hin[(kbase + ar) * BB + ac];
    cpa16(&Bs[0 * 1024 + br0 * 64 + bc0], &g_WhhT[(size_t)(kbase + br0) * G4 + cbase + bc0]);
    cpa16(&Bs[0 * 1024 + br1 * 64 + bc1], &g_WhhT[(size_t)(kbase + br1) * G4 + cbase + bc1]);
    cp_commit();

    for (int it = 0; it < 32; it++) {
        int buf = it & 1;
        cp_wait0();
        // store dup'd A for this chunk
        float* ad = &As2[buf * 1024 + ar * 64 + ac * 2];
        *(float4*)(ad)     = make_float4(av.x, av.x, av.y, av.y);
        *(float4*)(ad + 4) = make_float4(av.z, av.z, av.w, av.w);
        __syncthreads();
        if (it + 1 < 32) {
            int kn = kbase + (it + 1) * 16;
            int nb = buf ^ 1;
            av = *(const float4*)&hin[(kn + ar) * BB + ac];
            cpa16(&Bs[nb * 1024 + br0 * 64 + bc0], &g_WhhT[(size_t)(kn + br0) * G4 + cbase + bc0]);
            cpa16(&Bs[nb * 1024 + br1 * 64 + bc1], &g_WhhT[(size_t)(kn + br1) * G4 + cbase + bc1]);
            cp_commit();
        }
        const float* A = &As2[buf * 1024];
        const float* B = &Bs[buf * 1024];
#pragma unroll
        for (int k = 0; k < 16; k++) {
            float4 qa0 = *(const float4*)&A[k * 64 + tb * 8];
            float4 qa1 = *(const float4*)&A[k * 64 + tb * 8 + 4];
            float4 bq  = *(const float4*)&B[k * 64 + tc * 4];
            ull b01 = pk2(bq.x, bq.y), b23 = pk2(bq.z, bq.w);
            ull a0 = pk2(qa0.x, qa0.y), a1 = pk2(qa0.z, qa0.w);
            ull a2 = pk2(qa1.x, qa1.y), a3 = pk2(qa1.z, qa1.w);
            fma2(acc[0][0], a0, b01); fma2(acc[0][1], a0, b23);
            fma2(acc[1][0], a1, b01); fma2(acc[1][1], a1, b23);
            fma2(acc[2][0], a2, b01); fma2(acc[2][1], a2, b23);
            fma2(acc[3][0], a3, b01); fma2(acc[3][1], a3, b23);
        }
        __syncthreads();
    }

    // write partials: gsp[kw][b][c_local]
#pragma unroll
    for (int i = 0; i < 4; i++) {
#pragma unroll
        for (int j = 0; j < 2; j++) {
            float2 v = up2(acc[i][j]);
            int b = tb * 4 + i;
            gsp[(kw * 32 + b) * 65 + tc * 4 + j * 2 + 0] = v.x;
            gsp[(kw * 32 + b) * 65 + tc * 4 + j * 2 + 1] = v.y;
        }
    }
    __syncthreads();

    // LSTM elementwise: 512 (b,u) pairs, 1 per thread
    {
        int b = tid & 31, uu = tid >> 5;  // uu 0..15
        float4 pr = *(const float4*)&g_preg[(size_t)(t * BB + b) * G4 + (u0 + uu) * 4];
        float gi = pr.x, gf = pr.y, gg = pr.z, go = pr.w;
#pragma unroll
        for (int w = 0; w < 4; w++) {
            const float* gp = &gsp[(w * 32 + b) * 65 + uu * 4];
            gi += gp[0]; gf += gp[1]; gg += gp[2]; go += gp[3];
        }
        float si = 1.0f / (1.0f + expf(-gi));
        float sf_ = 1.0f / (1.0f + expf(-gf));
        float so = 1.0f / (1.0f + expf(-go));
        float tg = tanhf(gg);
        int u = u0 + uu;
        float c = sf_ * g_cT[u * BB + b] + si * tg;
        float hnew = so * tanhf(c);
        g_cT[u * BB + b] = c;
        hout[u * BB + b] = hnew;
    }
}

// ---------------- decoder: out[b*T+t][s] = h_t[b] . dec_W[s] + dec_b[s] ----------------
__global__ __launch_bounds__(256) void k_dec(const float* __restrict__ decW,
                                             const float* __restrict__ decb,
                                             float* __restrict__ out) {
    __shared__ __align__(16) float As[16][32];
    __shared__ __align__(16) float Bs[16][68];
    int t = blockIdx.y, s0 = blockIdx.x * 64;
    int tid = threadIdx.x;
    int tn = tid & 31, tm = tid >> 5;
    int brow = tid >> 2;
    int bkq = (tid & 3) * 4;
    ull acc[2][2] = {};

    for (int k0 = 0; k0 < HH; k0 += 16) {
#pragma unroll
        for (int l = 0; l < 2; l++) {
            int e = tid + l * 256;
            As[e >> 5][e & 31] = g_hall[((size_t)t * HH + k0 + (e >> 5)) * BB + (e & 31)];
        }
        float4 bv = *(const float4*)&decW[(size_t)(s0 + brow) * HH + k0 + bkq];
        Bs[bkq + 0][brow] = bv.x; Bs[bkq + 1][brow] = bv.y;
        Bs[bkq + 2][brow] = bv.z; Bs[bkq + 3][brow] = bv.w;
        __syncthreads();
#pragma unroll
        for (int k = 0; k < 16; k++) {
            float4 a = *(const float4*)&As[k][tm * 4];
            float2 b = *(const float2*)&Bs[k][tn * 2];
            ull ap0 = pk2(a.x, a.y), ap1 = pk2(a.z, a.w);
            ull bd0 = pk2(b.x, b.x), bd1 = pk2(b.y, b.y);
            fma2(acc[0][0], ap0, bd0); fma2(acc[0][1], ap0, bd1);
            fma2(acc[1][0], ap1, bd0); fma2(acc[1][1], ap1, bd1);
        }
        __syncthreads();
    }
#pragma unroll
    for (int p = 0; p < 2; p++) {
#pragma unroll
        for (int j = 0; j < 2; j++) {
            float2 v = up2(acc[p][j]);
            int s = s0 + tn * 2 + j;
            int b0i = tm * 4 + p * 2;
            out[(b0i * TT + t) * SS + s]       = v.x + decb[s];
            out[((b0i + 1) * TT + t) * SS + s] = v.y + decb[s];
        }
    }
}

// ---------------- final state write-out ----------------
__global__ void k_finish(float* __restrict__ out, int out_size) {
    int i = blockIdx.x * blockDim.x + threadIdx.x;
    if (i < HH * BB) {
        int b = i / HH, k = i % HH;
        int base = TB * SS;
        const float* hlast = &g_hall[(size_t)(TT - 1) * HH * BB];
        if (base + i < out_size) out[base + i] = hlast[k * BB + b];
        if (base + HH * BB + i < out_size) out[base + HH * BB + i] = g_cT[k * BB + b];
    }
}

extern "C" void kernel_launch(void* const* d_in, const int* in_sizes, int n_in,
                              void* d_out, int out_size) {
    const float* in1  = (const float*)d_in[0];
    const float* in2  = (const float*)d_in[1];
    const float* h0   = (const float*)d_in[2];
    const float* c0   = (const float*)d_in[3];
    const int*   rt   = (const int*)  d_in[4];
    const float* m1W  = (const float*)d_in[5];
    const float* m1b  = (const float*)d_in[6];
    const float* m2W  = (const float*)d_in[7];
    const float* m2b  = (const float*)d_in[8];
    const float* encW = (const float*)d_in[9];
    const float* encb = (const float*)d_in[10];
    const float* Wih  = (const float*)d_in[11];
    const float* Whh  = (const float*)d_in[12];
    const float* bih  = (const float*)d_in[13];
    const float* bhh  = (const float*)d_in[14];
    const float* decW = (const float*)d_in[15];
    const float* decb = (const float*)d_in[16];
    float* out = (float*)d_out;

    static int attr_done = 0;
    const int STEP_SMEM = (8192 + 8192 + 4 * 32 * 65) * 4;  // 98816 B
    if (!attr_done) {
        cudaFuncSetAttribute(k_step, cudaFuncAttributeMaxDynamicSharedMemorySize, STEP_SMEM);
        attr_done = 1;
    }

    float* whhT; cudaGetSymbolAddress((void**)&whhT, g_WhhT);
    float* wihT; cudaGetSymbolAddress((void**)&wihT, g_WihT);

    k_init<<<(HH * BB + 255) / 256, 256>>>(h0, c0);
    k_fused<<<(TB + 127) / 128, 128>>>(in1, in2, m1W, m1b, m2W, m2b);
    k_encode<<<TB, 256>>>(encW, encb, rt);
    k_wt<<<dim3(G4 / 32, HH / 32), dim3(32, 8)>>>(Whh, whhT);
    k_wt<<<dim3(G4 / 32, HH / 32), dim3(32, 8)>>>(Wih, wihT);
    k_xt<<<dim3(TB / 32, HH / 32), dim3(32, 8)>>>();
    k_pregemm<<<dim3(G4 / 128, TB / 128), 256, 4 * 2048 * 4>>>(bih, bhh);
    for (int t = 0; t < TT; t++)
        k_step<<<HH / 16, 512, STEP_SMEM>>>(t);
    k_dec<<<dim3(SS / 64, TT), 256>>>(decW, decb, out);
    k_finish<<<(HH * BB + 255) / 256, 256>>>(out, out_size);
}

// round 8
// speedup vs baseline: 3.0789x; 1.9767x over previous
#include <cuda_runtime.h>
#include <cuda_bf16.h>
#include <math.h>
#include <stdint.h>

#define BB 32
#define TT 200
#define HH 2048
#define G4 8192   // 4*H
#define SS 256
#define TB 6400   // T*B
#define FF 20
#define NCH 64    // K chunks of 32

typedef unsigned long long ull;

// ---- f32x2 packed-FMA helpers (for k_dec) ----
__device__ __forceinline__ ull pk2(float lo, float hi) {
    ull r; asm("mov.b64 %0, {%1, %2};" : "=l"(r) : "f"(lo), "f"(hi)); return r;
}
__device__ __forceinline__ void fma2(ull& d, ull a, ull b) {
    asm("fma.rn.f32x2 %0, %1, %2, %0;" : "+l"(d) : "l"(a), "l"(b));
}
__device__ __forceinline__ float2 up2(ull v) {
    float2 r; asm("mov.b64 {%0, %1}, %2;" : "=f"(r.x), "=f"(r.y) : "l"(v)); return r;
}

// ---- cp.async ----
__device__ __forceinline__ void cpa16s(uint32_t dst, const void* src) {
    asm volatile("cp.async.cg.shared.global [%0], [%1], 16;" :: "r"(dst), "l"(src));
}
__device__ __forceinline__ void cp_commit() { asm volatile("cp.async.commit_group;"); }

__device__ __forceinline__ uint32_t smem_u32(const void* p) {
    return (uint32_t)__cvta_generic_to_shared(p);
}
// 64B-row tile swizzle: XOR k-offset by bits 7-9 (row>>1) -> conflict-free ldmatrix
__device__ __forceinline__ uint32_t sw64(uint32_t off) { return off ^ (((off >> 7) & 7u) << 4); }

// ---- ldmatrix / mma.sync (baseline PTX, works on sm_103 non-'a') ----
__device__ __forceinline__ void ldsm_x4(uint32_t* r, uint32_t addr) {
    asm volatile("ldmatrix.sync.aligned.m8n8.x4.shared.b16 {%0,%1,%2,%3}, [%4];"
                 : "=r"(r[0]), "=r"(r[1]), "=r"(r[2]), "=r"(r[3]) : "r"(addr));
}
__device__ __forceinline__ void ldsm_x2(uint32_t* r, uint32_t addr) {
    asm volatile("ldmatrix.sync.aligned.m8n8.x2.shared.b16 {%0,%1}, [%2];"
                 : "=r"(r[0]), "=r"(r[1]) : "r"(addr));
}
__device__ __forceinline__ void mma_bf16(float* c, const uint32_t* a, const uint32_t* b) {
    asm volatile(
        "mma.sync.aligned.m16n8k16.row.col.f32.bf16.bf16.f32 "
        "{%0,%1,%2,%3}, {%4,%5,%6,%7}, {%8,%9}, {%0,%1,%2,%3};"
        : "+f"(c[0]), "+f"(c[1]), "+f"(c[2]), "+f"(c[3])
        : "r"(a[0]), "r"(a[1]), "r"(a[2]), "r"(a[3]), "r"(b[0]), "r"(b[1]));
}

// ---- scratch (device globals: allocation-free rule) ----
__device__ __align__(128) float g_fused[TB * FF];
__device__ __align__(128) float g_X[TB * HH];                       // [tb][h]
__device__ __align__(128) __nv_bfloat16 g_Xh[(size_t)NCH * TB * 32];  // chunk-major X hi
__device__ __align__(128) __nv_bfloat16 g_Xl[(size_t)NCH * TB * 32];  // chunk-major X lo
__device__ __align__(128) __nv_bfloat16 g_Wh[(size_t)NCH * G4 * 32];  // Wih hi (gate-interleaved cols)
__device__ __align__(128) __nv_bfloat16 g_Wl[(size_t)NCH * G4 * 32];  // Wih lo
__device__ __align__(128) __nv_bfloat16 g_Uh[(size_t)NCH * G4 * 32];  // Whh hi
__device__ __align__(128) __nv_bfloat16 g_Ul[(size_t)NCH * G4 * 32];  // Whh lo
__device__ __align__(128) float g_bsum[G4];                         // interleaved bias
__device__ __align__(128) float g_preg[(size_t)TB * G4];            // [tb][c], c = u*4+g
__device__ __align__(128) float g_cT[HH * BB];                      // [u][b]
__device__ __align__(128) float g_hall[(size_t)TT * HH * BB];       // [t][u][b]
__device__ __align__(128) __nv_bfloat16 g_hsp[2][NCH][2][32][32];   // [parity][chunk][hi/lo][b][kk]

// ---------------- init: c transposed, h0 split ----------------
__global__ void k_init(const float* __restrict__ h0, const float* __restrict__ c0) {
    int i = blockIdx.x * blockDim.x + threadIdx.x;
    if (i < HH * BB) {
        int b = i >> 11, u = i & 2047;
        g_cT[u * BB + b] = c0[i];
        float x = h0[i];
        __nv_bfloat16 h = __float2bfloat16(x);
        __nv_bfloat16 l = __float2bfloat16(x - __bfloat162float(h));
        g_hsp[0][u >> 5][0][b][u & 31] = h;
        g_hsp[0][u >> 5][1][b][u & 31] = l;
    }
}

// ---------------- fused = [x1@m1^T+b1 , x2@m2^T+b2] ----------------
__global__ void k_fused(const float* __restrict__ in1, const float* __restrict__ in2,
                        const float* __restrict__ m1W, const float* __restrict__ m1b,
                        const float* __restrict__ m2W, const float* __restrict__ m2b) {
    int idx = blockIdx.x * blockDim.x + threadIdx.x;
    if (idx >= TB) return;
    int t = idx / BB, b = idx % BB;
    float x0 = in1[(b * TT + t) * 2 + 0];
    float x1 = in1[(b * TT + t) * 2 + 1];
    float x2 = in2[b * TT + t];
#pragma unroll
    for (int j = 0; j < 10; j++)
        g_fused[idx * FF + j] = m1W[j * 2] * x0 + m1W[j * 2 + 1] * x1 + m1b[j];
#pragma unroll
    for (int j = 0; j < 10; j++)
        g_fused[idx * FF + 10 + j] = m2W[j] * x2 + m2b[j];
}

// ---------------- expert encode: X = fused @ enc_W[skill] + enc_b[skill] ----------------
__global__ __launch_bounds__(256) void k_encode(const float* __restrict__ encW,
                                                const float* __restrict__ encb,
                                                const int* __restrict__ routers) {
    int idx = blockIdx.x;
    int t = idx / BB, b = idx % BB;
    int skill = routers[b * TT + t];
    __shared__ float sf[FF];
    if (threadIdx.x < FF) sf[threadIdx.x] = g_fused[idx * FF + threadIdx.x];
    __syncthreads();
    const float* Wbase = encW + (size_t)skill * FF * HH;
    const float* bbase = encb + skill * HH;
    for (int h = threadIdx.x; h < HH; h += 256) {
        float acc = bbase[h];
#pragma unroll
        for (int f = 0; f < FF; f++) acc += sf[f] * Wbase[f * HH + h];
        g_X[idx * HH + h] = acc;
    }
}

// ---------------- split X into chunk-major bf16 hi/lo ----------------
__global__ __launch_bounds__(256) void k_splitX() {
    int m = blockIdx.x * 256 + threadIdx.x;   // 0..6399
    int ch = blockIdx.y;                       // 0..63
    const float* src = &g_X[(size_t)m * HH + ch * 32];
    union { __nv_bfloat16 b[32]; uint4 v[4]; } ph, pl;
#pragma unroll
    for (int i = 0; i < 32; i++) {
        float x = src[i];
        __nv_bfloat16 h = __float2bfloat16(x);
        ph.b[i] = h;
        pl.b[i] = __float2bfloat16(x - __bfloat162float(h));
    }
    size_t o = ((size_t)ch * TB + m) * 32;
#pragma unroll
    for (int i = 0; i < 4; i++) {
        *(uint4*)&g_Xh[o + i * 8] = ph.v[i];
        *(uint4*)&g_Xl[o + i * 8] = pl.v[i];
    }
}

// ---------------- split weights (gate-interleaved cols c=u*4+g) into chunk-major hi/lo ----------------
__global__ __launch_bounds__(256) void k_splitW(const float* __restrict__ W,
                                                __nv_bfloat16* __restrict__ dh,
                                                __nv_bfloat16* __restrict__ dl,
                                                const float* __restrict__ b1,
                                                const float* __restrict__ b2,
                                                int do_bias) {
    int c = blockIdx.x * 256 + threadIdx.x;   // 0..8191
    int ch = blockIdx.y;                       // 0..63
    int j = (c & 3) * HH + (c >> 2);
    if (do_bias && ch == 0) g_bsum[c] = b1[j] + b2[j];
    const float* src = &W[(size_t)j * HH + ch * 32];
    union { __nv_bfloat16 b[32]; uint4 v[4]; } ph, pl;
#pragma unroll
    for (int i = 0; i < 32; i++) {
        float x = src[i];
        __nv_bfloat16 h = __float2bfloat16(x);
        ph.b[i] = h;
        pl.b[i] = __float2bfloat16(x - __bfloat162float(h));
    }
    size_t o = ((size_t)ch * G4 + c) * 32;
#pragma unroll
    for (int i = 0; i < 4; i++) {
        *(uint4*)&dh[o + i * 8] = ph.v[i];
        *(uint4*)&dl[o + i * 8] = pl.v[i];
    }
}

// ---------------- HMMA pregemm: preg = split3(X @ Wih^T) + bias  [6400 x 8192] ----------------
// 128x128 CTA tile, 8 warps (2m x 4n), 32-K chunks, cp.async double-buffered.
__global__ __launch_bounds__(256) void k_hmma() {
    extern __shared__ char dsm[];   // [2][Ah 8K | Al 8K | Bh 8K | Bl 8K] = 64KB
    __shared__ float sbias[128];
    int tid = threadIdx.x, wid = tid >> 5, lane = tid & 31;
    int wm = wid & 1, wn = wid >> 1;
    int m0 = blockIdx.y * 128, n0 = blockIdx.x * 128;
    uint32_t sb = smem_u32(dsm);
    if (tid < 128) sbias[tid] = g_bsum[n0 + tid];

    auto stage = [&](int ch, int buf) {
        uint32_t tb = sb + buf * 32768;
        const char* sAh = (const char*)g_Xh + ((size_t)ch * TB + m0) * 64;
        const char* sAl = (const char*)g_Xl + ((size_t)ch * TB + m0) * 64;
        const char* sBh = (const char*)g_Wh + ((size_t)ch * G4 + n0) * 64;
        const char* sBl = (const char*)g_Wl + ((size_t)ch * G4 + n0) * 64;
#pragma unroll
        for (int i = 0; i < 2; i++) {
            uint32_t off = (uint32_t)(tid + i * 256) * 16;
            uint32_t so = sw64(off);
            cpa16s(tb + so,         sAh + off);
            cpa16s(tb + 8192 + so,  sAl + off);
            cpa16s(tb + 16384 + so, sBh + off);
            cpa16s(tb + 24576 + so, sBl + off);
        }
        cp_commit();
    };

    float C[4][4][4] = {};
    stage(0, 0);
    for (int it = 0; it < NCH; it++) {
        int buf = it & 1;
        if (it + 1 < NCH) {
            stage(it + 1, buf ^ 1);
            asm volatile("cp.async.wait_group 1;" ::: "memory");
        } else {
            asm volatile("cp.async.wait_group 0;" ::: "memory");
        }
        __syncthreads();
        uint32_t TA_h = sb + buf * 32768;
        uint32_t TA_l = TA_h + 8192;
        uint32_t TB_h = TA_h + 16384;
        uint32_t TB_l = TA_h + 24576;
#pragma unroll
        for (int ks = 0; ks < 2; ks++) {
            uint32_t bh[4][2], bl[4][2];
            uint32_t kbB = ks * 32 + ((lane >> 3) & 1) * 16;
#pragma unroll
            for (int nt = 0; nt < 4; nt++) {
                uint32_t offB = (uint32_t)(wn * 32 + nt * 8 + (lane & 7)) * 64 + kbB;
                ldsm_x2(bh[nt], TB_h + sw64(offB));
                ldsm_x2(bl[nt], TB_l + sw64(offB));
            }
            uint32_t kbA = ks * 32 + ((lane >> 4) & 1) * 16;
#pragma unroll
            for (int mt = 0; mt < 4; mt++) {
                uint32_t offA = (uint32_t)(wm * 64 + mt * 16 + (lane & 15)) * 64 + kbA;
                uint32_t ah[4], al[4];
                ldsm_x4(ah, TA_h + sw64(offA));
                ldsm_x4(al, TA_l + sw64(offA));
#pragma unroll
                for (int nt = 0; nt < 4; nt++) {
                    mma_bf16(C[mt][nt], ah, bh[nt]);
                    mma_bf16(C[mt][nt], ah, bl[nt]);
                    mma_bf16(C[mt][nt], al, bh[nt]);
                }
            }
        }
        __syncthreads();
    }

    // epilogue: add bias, write float2 pairs
#pragma unroll
    for (int mt = 0; mt < 4; mt++) {
#pragma unroll
        for (int nt = 0; nt < 4; nt++) {
            int cl = wn * 32 + nt * 8 + (lane & 3) * 2;
            int r0 = m0 + wm * 64 + mt * 16 + (lane >> 2);
            float b0 = sbias[cl], b1v = sbias[cl + 1];
            *(float2*)&g_preg[(size_t)r0 * G4 + n0 + cl] =
                make_float2(C[mt][nt][0] + b0, C[mt][nt][1] + b1v);
            *(float2*)&g_preg[(size_t)(r0 + 8) * G4 + n0 + cl] =
                make_float2(C[mt][nt][2] + b0, C[mt][nt][3] + b1v);
        }
    }
}

// ---------------- per-step: gates = preg + split3(h@Whh^T); LSTM elementwise ----------------
// 256 thr (8 warps x 8 cols), CTA covers 16 u (64 interleaved cols). h split double-buffered by parity.
__global__ __launch_bounds__(256) void k_step(int t) {
    __shared__ __align__(16) char sbuf[2][12288];  // Ah 2K | Al 2K | Bh 4K | Bl 4K
    __shared__ float gs[32][68];
    int tid = threadIdx.x, wid = tid >> 5, lane = tid & 31;
    int u0 = blockIdx.x * 16;
    int c0 = u0 * 4;
    int p_in = t & 1, p_out = (t + 1) & 1;
    uint32_t sb = smem_u32(&sbuf[0][0]);

    auto stage = [&](int ch, int buf) {
        uint32_t tb = sb + buf * 12288;
        const char* sA = (const char*)&g_hsp[p_in][ch][0][0][0];  // 4KB (hi then lo)
        {
            uint32_t off = (uint32_t)tid * 16;  // 0..4095
            cpa16s(tb + (off & 2048) + sw64(off & 2047), sA + off);
        }
        const char* sBh = (const char*)g_Uh + ((size_t)ch * G4 + c0) * 64;
        const char* sBl = (const char*)g_Ul + ((size_t)ch * G4 + c0) * 64;
        {
            uint32_t off = (uint32_t)tid * 16;  // 0..4095
            cpa16s(tb + 4096 + sw64(off), sBh + off);
            cpa16s(tb + 8192 + sw64(off), sBl + off);
        }
        cp_commit();
    };

    float C[2][4] = {};
    stage(0, 0);
    for (int it = 0; it < NCH; it++) {
        int buf = it & 1;
        if (it + 1 < NCH) {
            stage(it + 1, buf ^ 1);
            asm volatile("cp.async.wait_group 1;" ::: "memory");
        } else {
            asm volatile("cp.async.wait_group 0;" ::: "memory");
        }
        __syncthreads();
        uint32_t TA_h = sb + buf * 12288;
        uint32_t TA_l = TA_h + 2048;
        uint32_t TB_h = TA_h + 4096;
        uint32_t TB_l = TA_h + 8192;
#pragma unroll
        for (int ks = 0; ks < 2; ks++) {
            uint32_t bh[2], bl[2];
            uint32_t offB = (uint32_t)(wid * 8 + (lane & 7)) * 64 + ks * 32 + ((lane >> 3) & 1) * 16;
            ldsm_x2(bh, TB_h + sw64(offB));
            ldsm_x2(bl, TB_l + sw64(offB));
            uint32_t kbA = ks * 32 + ((lane >> 4) & 1) * 16;
#pragma unroll
            for (int mt = 0; mt < 2; mt++) {
                uint32_t offA = (uint32_t)(mt * 16 + (lane & 15)) * 64 + kbA;
                uint32_t ah[4], al[4];
                ldsm_x4(ah, TA_h + sw64(offA));
                ldsm_x4(al, TA_l + sw64(offA));
                mma_bf16(C[mt], ah, bh);
                mma_bf16(C[mt], ah, bl);
                mma_bf16(C[mt], al, bh);
            }
        }
        __syncthreads();
    }

    // stage gate tile to smem
#pragma unroll
    for (int mt = 0; mt < 2; mt++) {
        int b0 = mt * 16 + (lane >> 2);
        int cl = wid * 8 + (lane & 3) * 2;
        gs[b0][cl] = C[mt][0];     gs[b0][cl + 1] = C[mt][1];
        gs[b0 + 8][cl] = C[mt][2]; gs[b0 + 8][cl + 1] = C[mt][3];
    }
    __syncthreads();

    // LSTM elementwise: 512 (b,u) pairs, 2 per thread
    float* __restrict__ hout = &g_hall[(size_t)t * HH * BB];
#pragma unroll
    for (int l = 0; l < 2; l++) {
        int p = tid + l * 256;
        int b = p & 31, uu = p >> 5;  // uu 0..15
        float4 pr = *(const float4*)&g_preg[(size_t)(t * BB + b) * G4 + (u0 + uu) * 4];
        float gi = pr.x + gs[b][uu * 4 + 0];
        float gf = pr.y + gs[b][uu * 4 + 1];
        float gg = pr.z + gs[b][uu * 4 + 2];
        float go = pr.w + gs[b][uu * 4 + 3];
        float si = 1.0f / (1.0f + expf(-gi));
        float sf_ = 1.0f / (1.0f + expf(-gf));
        float so = 1.0f / (1.0f + expf(-go));
        float tg = tanhf(gg);
        int u = u0 + uu;
        float c = sf_ * g_cT[u * BB + b] + si * tg;
        float hnew = so * tanhf(c);
        g_cT[u * BB + b] = c;
        hout[u * BB + b] = hnew;
        __nv_bfloat16 hh = __float2bfloat16(hnew);
        g_hsp[p_out][u >> 5][0][b][u & 31] = hh;
        g_hsp[p_out][u >> 5][1][b][u & 31] =
            __float2bfloat16(hnew - __bfloat162float(hh));
    }
}

// ---------------- decoder: out[b*T+t][s] = h_t[b] . dec_W[s] + dec_b[s] ----------------
__global__ __launch_bounds__(256) void k_dec(const float* __restrict__ decW,
                                             const float* __restrict__ decb,
                                             float* __restrict__ out) {
    __shared__ __align__(16) float As[16][32];
    __shared__ __align__(16) float Bs[16][68];
    int t = blockIdx.y, s0 = blockIdx.x * 64;
    int tid = threadIdx.x;
    int tn = tid & 31, tm = tid >> 5;
    int brow = tid >> 2;
    int bkq = (tid & 3) * 4;
    ull acc[2][2] = {};

    for (int k0 = 0; k0 < HH; k0 += 16) {
#pragma unroll
        for (int l = 0; l < 2; l++) {
            int e = tid + l * 256;
            As[e >> 5][e & 31] = g_hall[((size_t)t * HH + k0 + (e >> 5)) * BB + (e & 31)];
        }
        float4 bv = *(const float4*)&decW[(size_t)(s0 + brow) * HH + k0 + bkq];
        Bs[bkq + 0][brow] = bv.x; Bs[bkq + 1][brow] = bv.y;
        Bs[bkq + 2][brow] = bv.z; Bs[bkq + 3][brow] = bv.w;
        __syncthreads();
#pragma unroll
        for (int k = 0; k < 16; k++) {
            float4 a = *(const float4*)&As[k][tm * 4];
            float2 b = *(const float2*)&Bs[k][tn * 2];
            ull ap0 = pk2(a.x, a.y), ap1 = pk2(a.z, a.w);
            ull bd0 = pk2(b.x, b.x), bd1 = pk2(b.y, b.y);
            fma2(acc[0][0], ap0, bd0); fma2(acc[0][1], ap0, bd1);
            fma2(acc[1][0], ap1, bd0); fma2(acc[1][1], ap1, bd1);
        }
        __syncthreads();
    }
#pragma unroll
    for (int p = 0; p < 2; p++) {
#pragma unroll
        for (int j = 0; j < 2; j++) {
            float2 v = up2(acc[p][j]);
            int s = s0 + tn * 2 + j;
            int b0i = tm * 4 + p * 2;
            out[(b0i * TT + t) * SS + s]       = v.x + decb[s];
            out[((b0i + 1) * TT + t) * SS + s] = v.y + decb[s];
        }
    }
}

// ---------------- final state write-out ----------------
__global__ void k_finish(float* __restrict__ out, int out_size) {
    int i = blockIdx.x * blockDim.x + threadIdx.x;
    if (i < HH * BB) {
        int b = i / HH, k = i % HH;
        int base = TB * SS;
        const float* hlast = &g_hall[(size_t)(TT - 1) * HH * BB];
        if (base + i < out_size) out[base + i] = hlast[k * BB + b];
        if (base + HH * BB + i < out_size) out[base + HH * BB + i] = g_cT[k * BB + b];
    }
}

extern "C" void kernel_launch(void* const* d_in, const int* in_sizes, int n_in,
                              void* d_out, int out_size) {
    const float* in1  = (const float*)d_in[0];
    const float* in2  = (const float*)d_in[1];
    const float* h0   = (const float*)d_in[2];
    const float* c0   = (const float*)d_in[3];
    const int*   rt   = (const int*)  d_in[4];
    const float* m1W  = (const float*)d_in[5];
    const float* m1b  = (const float*)d_in[6];
    const float* m2W  = (const float*)d_in[7];
    const float* m2b  = (const float*)d_in[8];
    const float* encW = (const float*)d_in[9];
    const float* encb = (const float*)d_in[10];
    const float* Wih  = (const float*)d_in[11];
    const float* Whh  = (const float*)d_in[12];
    const float* bih  = (const float*)d_in[13];
    const float* bhh  = (const float*)d_in[14];
    const float* decW = (const float*)d_in[15];
    const float* decb = (const float*)d_in[16];
    float* out = (float*)d_out;

    static int attr_done = 0;
    const int HMMA_SMEM = 65536;
    if (!attr_done) {
        cudaFuncSetAttribute(k_hmma, cudaFuncAttributeMaxDynamicSharedMemorySize, HMMA_SMEM);
        attr_done = 1;
    }

    __nv_bfloat16 *wh, *wl, *uh, *ul;
    cudaGetSymbolAddress((void**)&wh, g_Wh);
    cudaGetSymbolAddress((void**)&wl, g_Wl);
    cudaGetSymbolAddress((void**)&uh, g_Uh);
    cudaGetSymbolAddress((void**)&ul, g_Ul);

    k_init<<<(HH * BB + 255) / 256, 256>>>(h0, c0);
    k_fused<<<(TB + 127) / 128, 128>>>(in1, in2, m1W, m1b, m2W, m2b);
    k_encode<<<TB, 256>>>(encW, encb, rt);
    k_splitX<<<dim3(TB / 256, NCH), 256>>>();
    k_splitW<<<dim3(G4 / 256, NCH), 256>>>(Wih, wh, wl, bih, bhh, 1);
    k_splitW<<<dim3(G4 / 256, NCH), 256>>>(Whh, uh, ul, bih, bhh, 0);
    k_hmma<<<dim3(G4 / 128, TB / 128), 256, HMMA_SMEM>>>();
    for (int t = 0; t < TT; t++)
        k_step<<<HH / 16, 256>>>(t);
    k_dec<<<dim3(SS / 64, TT), 256>>>(decW, decb, out);
    k_finish<<<(HH * BB + 255) / 256, 256>>>(out, out_size);
}

// round 9
// speedup vs baseline: 3.3295x; 1.0814x over previous
#include <cuda_runtime.h>
#include <cuda_bf16.h>
#include <math.h>
#include <stdint.h>

#define BB 32
#define TT 200
#define HH 2048
#define G4 8192   // 4*H
#define SS 256
#define TB 6400   // T*B
#define FF 20
#define NCH 64    // K chunks of 32 (pregemm)
#define NC64 32   // K chunks of 64 (scan)

typedef unsigned long long ull;

// ---- f32x2 packed-FMA helpers (for k_dec) ----
__device__ __forceinline__ ull pk2(float lo, float hi) {
    ull r; asm("mov.b64 %0, {%1, %2};" : "=l"(r) : "f"(lo), "f"(hi)); return r;
}
__device__ __forceinline__ void fma2(ull& d, ull a, ull b) {
    asm("fma.rn.f32x2 %0, %1, %2, %0;" : "+l"(d) : "l"(a), "l"(b));
}
__device__ __forceinline__ float2 up2(ull v) {
    float2 r; asm("mov.b64 {%0, %1}, %2;" : "=f"(r.x), "=f"(r.y) : "l"(v)); return r;
}

// ---- cp.async ----
__device__ __forceinline__ void cpa16s(uint32_t dst, const void* src) {
    asm volatile("cp.async.cg.shared.global [%0], [%1], 16;" :: "r"(dst), "l"(src));
}
__device__ __forceinline__ void cp_commit() { asm volatile("cp.async.commit_group;"); }

__device__ __forceinline__ uint32_t smem_u32(const void* p) {
    return (uint32_t)__cvta_generic_to_shared(p);
}
// swizzles: 64B rows and 128B rows
__device__ __forceinline__ uint32_t sw64(uint32_t off)  { return off ^ (((off >> 7) & 7u) << 4); }
__device__ __forceinline__ uint32_t sw128(uint32_t off) { return off ^ ((off >> 3) & 0x70u); }

// ---- ldmatrix / mma.sync (baseline PTX, legal on sm_103 non-'a') ----
__device__ __forceinline__ void ldsm_x4(uint32_t* r, uint32_t addr) {
    asm volatile("ldmatrix.sync.aligned.m8n8.x4.shared.b16 {%0,%1,%2,%3}, [%4];"
                 : "=r"(r[0]), "=r"(r[1]), "=r"(r[2]), "=r"(r[3]) : "r"(addr));
}
__device__ __forceinline__ void ldsm_x2(uint32_t* r, uint32_t addr) {
    asm volatile("ldmatrix.sync.aligned.m8n8.x2.shared.b16 {%0,%1}, [%2];"
                 : "=r"(r[0]), "=r"(r[1]) : "r"(addr));
}
__device__ __forceinline__ void mma_bf16(float* c, const uint32_t* a, const uint32_t* b) {
    asm volatile(
        "mma.sync.aligned.m16n8k16.row.col.f32.bf16.bf16.f32 "
        "{%0,%1,%2,%3}, {%4,%5,%6,%7}, {%8,%9}, {%0,%1,%2,%3};"
        : "+f"(c[0]), "+f"(c[1]), "+f"(c[2]), "+f"(c[3])
        : "r"(a[0]), "r"(a[1]), "r"(a[2]), "r"(a[3]), "r"(b[0]), "r"(b[1]));
}

// ---- scratch (device globals: allocation-free rule) ----
__device__ __align__(128) float g_fused[TB * FF];
__device__ __align__(128) float g_X[TB * HH];
__device__ __align__(128) __nv_bfloat16 g_Xh[(size_t)NCH * TB * 32];   // chunk32-major X hi
__device__ __align__(128) __nv_bfloat16 g_Xl[(size_t)NCH * TB * 32];   // chunk32-major X lo
__device__ __align__(128) __nv_bfloat16 g_Wh[(size_t)NCH * G4 * 32];   // Wih hi (interleaved cols)
__device__ __align__(128) __nv_bfloat16 g_Wl[(size_t)NCH * G4 * 32];   // Wih lo
__device__ __align__(128) __nv_bfloat16 g_U2h[(size_t)NC64 * G4 * 64]; // Whh hi, chunk64
__device__ __align__(128) __nv_bfloat16 g_U2l[(size_t)NC64 * G4 * 64]; // Whh lo, chunk64
__device__ __align__(128) float g_bsum[G4];
__device__ __align__(128) float g_preg[(size_t)TB * G4];               // [tb][c], c=u*4+g
__device__ __align__(128) float g_cT[HH * BB];                         // [u][b]
__device__ __align__(128) float g_hall[(size_t)TT * HH * BB];          // [t][u][b]
__device__ __align__(128) __nv_bfloat16 g_hsp[2][NC64][2][32][64];     // [parity][ch64][hi/lo][b][kk]

// ---------------- init: c transposed, h0 split ----------------
__global__ void k_init(const float* __restrict__ h0, const float* __restrict__ c0) {
    int i = blockIdx.x * blockDim.x + threadIdx.x;
    if (i < HH * BB) {
        int b = i >> 11, u = i & 2047;
        g_cT[u * BB + b] = c0[i];
        float x = h0[i];
        __nv_bfloat16 h = __float2bfloat16(x);
        __nv_bfloat16 l = __float2bfloat16(x - __bfloat162float(h));
        g_hsp[0][u >> 6][0][b][u & 63] = h;
        g_hsp[0][u >> 6][1][b][u & 63] = l;
    }
}

// ---------------- fused = [x1@m1^T+b1 , x2@m2^T+b2] ----------------
__global__ void k_fused(const float* __restrict__ in1, const float* __restrict__ in2,
                        const float* __restrict__ m1W, const float* __restrict__ m1b,
                        const float* __restrict__ m2W, const float* __restrict__ m2b) {
    int idx = blockIdx.x * blockDim.x + threadIdx.x;
    if (idx >= TB) return;
    int t = idx / BB, b = idx % BB;
    float x0 = in1[(b * TT + t) * 2 + 0];
    float x1 = in1[(b * TT + t) * 2 + 1];
    float x2 = in2[b * TT + t];
#pragma unroll
    for (int j = 0; j < 10; j++)
        g_fused[idx * FF + j] = m1W[j * 2] * x0 + m1W[j * 2 + 1] * x1 + m1b[j];
#pragma unroll
    for (int j = 0; j < 10; j++)
        g_fused[idx * FF + 10 + j] = m2W[j] * x2 + m2b[j];
}

// ---------------- expert encode: X = fused @ enc_W[skill] + enc_b[skill] ----------------
__global__ __launch_bounds__(256) void k_encode(const float* __restrict__ encW,
                                                const float* __restrict__ encb,
                                                const int* __restrict__ routers) {
    int idx = blockIdx.x;
    int t = idx / BB, b = idx % BB;
    int skill = routers[b * TT + t];
    __shared__ float sf[FF];
    if (threadIdx.x < FF) sf[threadIdx.x] = g_fused[idx * FF + threadIdx.x];
    __syncthreads();
    const float* Wbase = encW + (size_t)skill * FF * HH;
    const float* bbase = encb + skill * HH;
    for (int h = threadIdx.x; h < HH; h += 256) {
        float acc = bbase[h];
#pragma unroll
        for (int f = 0; f < FF; f++) acc += sf[f] * Wbase[f * HH + h];
        g_X[idx * HH + h] = acc;
    }
}

// ---------------- split X into chunk32-major bf16 hi/lo ----------------
__global__ __launch_bounds__(256) void k_splitX() {
    int m = blockIdx.x * 256 + threadIdx.x;
    int ch = blockIdx.y;
    const float* src = &g_X[(size_t)m * HH + ch * 32];
    union { __nv_bfloat16 b[32]; uint4 v[4]; } ph, pl;
#pragma unroll
    for (int i = 0; i < 32; i++) {
        float x = src[i];
        __nv_bfloat16 h = __float2bfloat16(x);
        ph.b[i] = h;
        pl.b[i] = __float2bfloat16(x - __bfloat162float(h));
    }
    size_t o = ((size_t)ch * TB + m) * 32;
#pragma unroll
    for (int i = 0; i < 4; i++) {
        *(uint4*)&g_Xh[o + i * 8] = ph.v[i];
        *(uint4*)&g_Xl[o + i * 8] = pl.v[i];
    }
}

// ---------------- split Wih (interleaved cols) into chunk32-major hi/lo + bias ----------------
__global__ __launch_bounds__(256) void k_splitW(const float* __restrict__ W,
                                                __nv_bfloat16* __restrict__ dh,
                                                __nv_bfloat16* __restrict__ dl,
                                                const float* __restrict__ b1,
                                                const float* __restrict__ b2,
                                                int do_bias) {
    int c = blockIdx.x * 256 + threadIdx.x;
    int ch = blockIdx.y;
    int j = (c & 3) * HH + (c >> 2);
    if (do_bias && ch == 0) g_bsum[c] = b1[j] + b2[j];
    const float* src = &W[(size_t)j * HH + ch * 32];
    union { __nv_bfloat16 b[32]; uint4 v[4]; } ph, pl;
#pragma unroll
    for (int i = 0; i < 32; i++) {
        float x = src[i];
        __nv_bfloat16 h = __float2bfloat16(x);
        ph.b[i] = h;
        pl.b[i] = __float2bfloat16(x - __bfloat162float(h));
    }
    size_t o = ((size_t)ch * G4 + c) * 32;
#pragma unroll
    for (int i = 0; i < 4; i++) {
        *(uint4*)&dh[o + i * 8] = ph.v[i];
        *(uint4*)&dl[o + i * 8] = pl.v[i];
    }
}

// ---------------- split Whh (interleaved cols) into chunk64-major hi/lo ----------------
__global__ __launch_bounds__(256) void k_splitW64(const float* __restrict__ W) {
    int c = blockIdx.x * 256 + threadIdx.x;
    int ch = blockIdx.y;   // 0..31
    int j = (c & 3) * HH + (c >> 2);
    const float* src = &W[(size_t)j * HH + ch * 64];
    union { __nv_bfloat16 b[64]; uint4 v[8]; } ph, pl;
#pragma unroll
    for (int i = 0; i < 64; i++) {
        float x = src[i];
        __nv_bfloat16 h = __float2bfloat16(x);
        ph.b[i] = h;
        pl.b[i] = __float2bfloat16(x - __bfloat162float(h));
    }
    size_t o = ((size_t)ch * G4 + c) * 64;
#pragma unroll
    for (int i = 0; i < 8; i++) {
        *(uint4*)&g_U2h[o + i * 8] = ph.v[i];
        *(uint4*)&g_U2l[o + i * 8] = pl.v[i];
    }
}

// ---------------- HMMA pregemm: preg = split3(X @ Wih^T) + bias  [6400 x 8192] ----------------
// 128x128 CTA tile, 8 warps (2m x 4n), 32-K chunks, 3-stage cp.async, one sync/chunk.
__global__ __launch_bounds__(256) void k_hmma() {
    extern __shared__ char dsm[];   // 3 x [Ah 8K | Al 8K | Bh 8K | Bl 8K] = 96KB
    __shared__ float sbias[128];
    int tid = threadIdx.x, wid = tid >> 5, lane = tid & 31;
    int wm = wid & 1, wn = wid >> 1;
    int m0 = blockIdx.y * 128, n0 = blockIdx.x * 128;
    uint32_t sb = smem_u32(dsm);
    if (tid < 128) sbias[tid] = g_bsum[n0 + tid];

    auto stage = [&](int ch, int buf) {
        uint32_t tb = sb + buf * 32768;
        const char* sAh = (const char*)g_Xh + ((size_t)ch * TB + m0) * 64;
        const char* sAl = (const char*)g_Xl + ((size_t)ch * TB + m0) * 64;
        const char* sBh = (const char*)g_Wh + ((size_t)ch * G4 + n0) * 64;
        const char* sBl = (const char*)g_Wl + ((size_t)ch * G4 + n0) * 64;
#pragma unroll
        for (int i = 0; i < 2; i++) {
            uint32_t off = (uint32_t)(tid + i * 256) * 16;
            uint32_t so = sw64(off);
            cpa16s(tb + so,         sAh + off);
            cpa16s(tb + 8192 + so,  sAl + off);
            cpa16s(tb + 16384 + so, sBh + off);
            cpa16s(tb + 24576 + so, sBl + off);
        }
        cp_commit();
    };

    float C[4][4][4] = {};
    stage(0, 0);
    stage(1, 1);
    for (int it = 0; it < NCH; it++) {
        if (it < NCH - 1) { asm volatile("cp.async.wait_group 1;" ::: "memory"); }
        else              { asm volatile("cp.async.wait_group 0;" ::: "memory"); }
        __syncthreads();
        if (it + 2 < NCH) stage(it + 2, (it + 2) % 3);
        int buf = it % 3;
        uint32_t TA_h = sb + buf * 32768;
        uint32_t TA_l = TA_h + 8192;
        uint32_t TB_h = TA_h + 16384;
        uint32_t TB_l = TA_h + 24576;
#pragma unroll
        for (int ks = 0; ks < 2; ks++) {
            uint32_t bh[4][2], bl[4][2];
            uint32_t kbB = ks * 32 + ((lane >> 3) & 1) * 16;
#pragma unroll
            for (int nt = 0; nt < 4; nt++) {
                uint32_t offB = (uint32_t)(wn * 32 + nt * 8 + (lane & 7)) * 64 + kbB;
                ldsm_x2(bh[nt], TB_h + sw64(offB));
                ldsm_x2(bl[nt], TB_l + sw64(offB));
            }
            uint32_t kbA = ks * 32 + ((lane >> 4) & 1) * 16;
#pragma unroll
            for (int mt = 0; mt < 4; mt++) {
                uint32_t offA = (uint32_t)(wm * 64 + mt * 16 + (lane & 15)) * 64 + kbA;
                uint32_t ah[4], al[4];
                ldsm_x4(ah, TA_h + sw64(offA));
                ldsm_x4(al, TA_l + sw64(offA));
#pragma unroll
                for (int nt = 0; nt < 4; nt++) {
                    mma_bf16(C[mt][nt], ah, bh[nt]);
                    mma_bf16(C[mt][nt], ah, bl[nt]);
                    mma_bf16(C[mt][nt], al, bh[nt]);
                }
            }
        }
    }

#pragma unroll
    for (int mt = 0; mt < 4; mt++) {
#pragma unroll
        for (int nt = 0; nt < 4; nt++) {
            int cl = wn * 32 + nt * 8 + (lane & 3) * 2;
            int r0 = m0 + wm * 64 + mt * 16 + (lane >> 2);
            float b0 = sbias[cl], b1v = sbias[cl + 1];
            *(float2*)&g_preg[(size_t)r0 * G4 + n0 + cl] =
                make_float2(C[mt][nt][0] + b0, C[mt][nt][1] + b1v);
            *(float2*)&g_preg[(size_t)(r0 + 8) * G4 + n0 + cl] =
                make_float2(C[mt][nt][2] + b0, C[mt][nt][3] + b1v);
        }
    }
}

// ---------------- per-step: gates = preg + split3(h@Whh^T); LSTM elementwise ----------------
// 256 thr, CTA = 64 interleaved cols (16 u). chunk K=64, 3-stage cp.async, one sync/chunk.
__global__ __launch_bounds__(256) void k_step(int t) {
    extern __shared__ char sstep[];   // 3 x [Ah 4K | Al 4K | Bh 8K | Bl 8K] = 72KB
    __shared__ float gs[32][68];
    int tid = threadIdx.x, wid = tid >> 5, lane = tid & 31;
    int u0 = blockIdx.x * 16;
    int c0 = u0 * 4;
    int p_in = t & 1, p_out = (t + 1) & 1;
    uint32_t sb = smem_u32(sstep);

    auto stage = [&](int ch, int buf) {
        uint32_t tb = sb + buf * 24576;
        const char* sA = (const char*)&g_hsp[p_in][ch][0][0][0];  // 8KB: hi 4K | lo 4K
#pragma unroll
        for (int i = 0; i < 2; i++) {
            uint32_t off = (uint32_t)(tid + i * 256) * 16;        // 0..8191
            cpa16s(tb + (off & 4096) + sw128(off & 4095), sA + off);
        }
        const char* sBh = (const char*)g_U2h + ((size_t)ch * G4 + c0) * 128;
        const char* sBl = (const char*)g_U2l + ((size_t)ch * G4 + c0) * 128;
#pragma unroll
        for (int i = 0; i < 2; i++) {
            uint32_t off = (uint32_t)(tid + i * 256) * 16;        // 0..8191
            uint32_t so = sw128(off);
            cpa16s(tb + 8192 + so,  sBh + off);
            cpa16s(tb + 16384 + so, sBl + off);
        }
        cp_commit();
    };

    float C[2][4] = {};
    stage(0, 0);
    stage(1, 1);
    for (int it = 0; it < NC64; it++) {
        if (it < NC64 - 1) { asm volatile("cp.async.wait_group 1;" ::: "memory"); }
        else               { asm volatile("cp.async.wait_group 0;" ::: "memory"); }
        __syncthreads();
        if (it + 2 < NC64) stage(it + 2, (it + 2) % 3);
        int buf = it % 3;
        uint32_t TA_h = sb + buf * 24576;
        uint32_t TA_l = TA_h + 4096;
        uint32_t TB_h = TA_h + 8192;
        uint32_t TB_l = TA_h + 16384;
#pragma unroll
        for (int ks = 0; ks < 4; ks++) {
            uint32_t bh[2], bl[2];
            uint32_t offB = (uint32_t)(wid * 8 + (lane & 7)) * 128 + ks * 32 + ((lane >> 3) & 1) * 16;
            ldsm_x2(bh, TB_h + sw128(offB));
            ldsm_x2(bl, TB_l + sw128(offB));
            uint32_t kbA = ks * 32 + ((lane >> 4) & 1) * 16;
#pragma unroll
            for (int mt = 0; mt < 2; mt++) {
                uint32_t offA = (uint32_t)(mt * 16 + (lane & 15)) * 128 + kbA;
                uint32_t ah[4], al[4];
                ldsm_x4(ah, TA_h + sw128(offA));
                ldsm_x4(al, TA_l + sw128(offA));
                mma_bf16(C[mt], ah, bh);
                mma_bf16(C[mt], ah, bl);
                mma_bf16(C[mt], al, bh);
            }
        }
    }

    // stage gate tile to smem
#pragma unroll
    for (int mt = 0; mt < 2; mt++) {
        int b0 = mt * 16 + (lane >> 2);
        int cl = wid * 8 + (lane & 3) * 2;
        gs[b0][cl] = C[mt][0];     gs[b0][cl + 1] = C[mt][1];
        gs[b0 + 8][cl] = C[mt][2]; gs[b0 + 8][cl + 1] = C[mt][3];
    }
    __syncthreads();

    // LSTM elementwise: 512 (b,u) pairs, 2 per thread
    float* __restrict__ hout = &g_hall[(size_t)t * HH * BB];
#pragma unroll
    for (int l = 0; l < 2; l++) {
        int p = tid + l * 256;
        int b = p & 31, uu = p >> 5;  // uu 0..15
        float4 pr = *(const float4*)&g_preg[(size_t)(t * BB + b) * G4 + (u0 + uu) * 4];
        float gi = pr.x + gs[b][uu * 4 + 0];
        float gf = pr.y + gs[b][uu * 4 + 1];
        float gg = pr.z + gs[b][uu * 4 + 2];
        float go = pr.w + gs[b][uu * 4 + 3];
        float si = 1.0f / (1.0f + expf(-gi));
        float sf_ = 1.0f / (1.0f + expf(-gf));
        float so = 1.0f / (1.0f + expf(-go));
        float tg = tanhf(gg);
        int u = u0 + uu;
        float c = sf_ * g_cT[u * BB + b] + si * tg;
        float hnew = so * tanhf(c);
        g_cT[u * BB + b] = c;
        hout[u * BB + b] = hnew;
        __nv_bfloat16 hh = __float2bfloat16(hnew);
        g_hsp[p_out][u >> 6][0][b][u & 63] = hh;
        g_hsp[p_out][u >> 6][1][b][u & 63] =
            __float2bfloat16(hnew - __bfloat162float(hh));
    }
}

// ---------------- decoder: out[b*T+t][s] = h_t[b] . dec_W[s] + dec_b[s] ----------------
__global__ __launch_bounds__(256) void k_dec(const float* __restrict__ decW,
                                             const float* __restrict__ decb,
                                             float* __restrict__ out) {
    __shared__ __align__(16) float As[16][32];
    __shared__ __align__(16) float Bs[16][68];
    int t = blockIdx.y, s0 = blockIdx.x * 64;
    int tid = threadIdx.x;
    int tn = tid & 31, tm = tid >> 5;
    int brow = tid >> 2;
    int bkq = (tid & 3) * 4;
    ull acc[2][2] = {};

    for (int k0 = 0; k0 < HH; k0 += 16) {
#pragma unroll
        for (int l = 0; l < 2; l++) {
            int e = tid + l * 256;
            As[e >> 5][e & 31] = g_hall[((size_t)t * HH + k0 + (e >> 5)) * BB + (e & 31)];
        }
        float4 bv = *(const float4*)&decW[(size_t)(s0 + brow) * HH + k0 + bkq];
        Bs[bkq + 0][brow] = bv.x; Bs[bkq + 1][brow] = bv.y;
        Bs[bkq + 2][brow] = bv.z; Bs[bkq + 3][brow] = bv.w;
        __syncthreads();
#pragma unroll
        for (int k = 0; k < 16; k++) {
            float4 a = *(const float4*)&As[k][tm * 4];
            float2 b = *(const float2*)&Bs[k][tn * 2];
            ull ap0 = pk2(a.x, a.y), ap1 = pk2(a.z, a.w);
            ull bd0 = pk2(b.x, b.x), bd1 = pk2(b.y, b.y);
            fma2(acc[0][0], ap0, bd0); fma2(acc[0][1], ap0, bd1);
            fma2(acc[1][0], ap1, bd0); fma2(acc[1][1], ap1, bd1);
        }
        __syncthreads();
    }
#pragma unroll
    for (int p = 0; p < 2; p++) {
#pragma unroll
        for (int j = 0; j < 2; j++) {
            float2 v = up2(acc[p][j]);
            int s = s0 + tn * 2 + j;
            int b0i = tm * 4 + p * 2;
            out[(b0i * TT + t) * SS + s]       = v.x + decb[s];
            out[((b0i + 1) * TT + t) * SS + s] = v.y + decb[s];
        }
    }
}

// ---------------- final state write-out ----------------
__global__ void k_finish(float* __restrict__ out, int out_size) {
    int i = blockIdx.x * blockDim.x + threadIdx.x;
    if (i < HH * BB) {
        int b = i / HH, k = i % HH;
        int base = TB * SS;
        const float* hlast = &g_hall[(size_t)(TT - 1) * HH * BB];
        if (base + i < out_size) out[base + i] = hlast[k * BB + b];
        if (base + HH * BB + i < out_size) out[base + HH * BB + i] = g_cT[k * BB + b];
    }
}

extern "C" void kernel_launch(void* const* d_in, const int* in_sizes, int n_in,
                              void* d_out, int out_size) {
    const float* in1  = (const float*)d_in[0];
    const float* in2  = (const float*)d_in[1];
    const float* h0   = (const float*)d_in[2];
    const float* c0   = (const float*)d_in[3];
    const int*   rt   = (const int*)  d_in[4];
    const float* m1W  = (const float*)d_in[5];
    const float* m1b  = (const float*)d_in[6];
    const float* m2W  = (const float*)d_in[7];
    const float* m2b  = (const float*)d_in[8];
    const float* encW = (const float*)d_in[9];
    const float* encb = (const float*)d_in[10];
    const float* Wih  = (const float*)d_in[11];
    const float* Whh  = (const float*)d_in[12];
    const float* bih  = (const float*)d_in[13];
    const float* bhh  = (const float*)d_in[14];
    const float* decW = (const float*)d_in[15];
    const float* decb = (const float*)d_in[16];
    float* out = (float*)d_out;

    static int attr_done = 0;
    const int HMMA_SMEM = 3 * 32768;   // 96KB
    const int STEP_SMEM = 3 * 24576;   // 72KB
    if (!attr_done) {
        cudaFuncSetAttribute(k_hmma, cudaFuncAttributeMaxDynamicSharedMemorySize, HMMA_SMEM);
        cudaFuncSetAttribute(k_step, cudaFuncAttributeMaxDynamicSharedMemorySize, STEP_SMEM);
        attr_done = 1;
    }

    __nv_bfloat16 *wh, *wl;
    cudaGetSymbolAddress((void**)&wh, g_Wh);
    cudaGetSymbolAddress((void**)&wl, g_Wl);

    k_init<<<(HH * BB + 255) / 256, 256>>>(h0, c0);
    k_fused<<<(TB + 127) / 128, 128>>>(in1, in2, m1W, m1b, m2W, m2b);
    k_encode<<<TB, 256>>>(encW, encb, rt);
    k_splitX<<<dim3(TB / 256, NCH), 256>>>();
    k_splitW<<<dim3(G4 / 256, NCH), 256>>>(Wih, wh, wl, bih, bhh, 1);
    k_splitW64<<<dim3(G4 / 256, NC64), 256>>>(Whh);
    k_hmma<<<dim3(G4 / 128, TB / 128), 256, HMMA_SMEM>>>();
    for (int t = 0; t < TT; t++)
        k_step<<<HH / 16, 256, STEP_SMEM>>>(t);
    k_dec<<<dim3(SS / 64, TT), 256>>>(decW, decb, out);
    k_finish<<<(HH * BB + 255) / 256, 256>>>(out, out_size);
}